// round 16
// baseline (speedup 1.0000x reference)
#include <cuda_runtime.h>
#include <cuda_fp16.h>

// ---------------------------------------------------------------------------
// ScatLayerj2: 2-level DTCWT scattering. Fused; fp16 intermediates;
// branch-split phase-2 warps with 4-row streaming (LDS.64).
// x (32,3,512,512) f32 -> Z (32,147,128,128) f32
// ---------------------------------------------------------------------------

typedef unsigned long long u64;

static __device__ __forceinline__ u64 pk2(float lo, float hi) {
    u64 r; asm("mov.b64 %0,{%1,%2};" : "=l"(r) : "f"(lo), "f"(hi)); return r;
}
static __device__ __forceinline__ float2 upk(u64 v) {
    float2 r; asm("mov.b64 {%0,%1},%2;" : "=f"(r.x), "=f"(r.y) : "l"(v)); return r;
}
static __device__ __forceinline__ void fmap(u64& d, u64 a, u64 b) {
    asm("fma.rn.f32x2 %0,%1,%2,%0;" : "+l"(d) : "l"(a), "l"(b));
}

static __device__ __forceinline__ int refl(int p, int l) {
    if (p < 0)  p = -1 - p;
    if (p >= l) p = 2 * l - 1 - p;
    return p;
}

static __device__ __forceinline__ float smag(float re, float im) {
    return sqrtf(re * re + im * im + 1e-4f) - 0.01f;
}

static __device__ __forceinline__ void q2c_mags(float v0x, float v0y, float v1x, float v1y,
                                                float& m_first, float& m_second) {
    const float s = 0.70710678118654752440f;
    float a = v0x * s, b = v0y * s, c = v1x * s, d = v1y * s;
    m_first  = smag(a - d, b + c);
    m_second = smag(a + d, b - c);
}

static __device__ __forceinline__ float to_f(float v)  { return v; }
static __device__ __forceinline__ float to_f(__half v) { return __half2float(v); }

// 16-wide window loaders (interior; c is a multiple of 4 elements)
static __device__ __forceinline__ void load16(const float* rowp, int c, float* w) {
#pragma unroll
    for (int j = 0; j < 4; j++) {
        float4 v = *(const float4*)(rowp + c + 4 * j);
        w[4*j] = v.x; w[4*j+1] = v.y; w[4*j+2] = v.z; w[4*j+3] = v.w;
    }
}
static __device__ __forceinline__ void load16(const __half* rowp, int c, float* w) {
    // c % 4 == 0 elements -> 8-byte aligned: uint2 loads only.
#pragma unroll
    for (int j = 0; j < 4; j++) {
        uint2 v = *(const uint2*)(rowp + c + 4 * j);
        const __half2* hv = (const __half2*)&v;
#pragma unroll
        for (int i = 0; i < 2; i++) {
            float2 f = __half22float2(hv[i]);
            w[4*j + 2*i] = f.x; w[4*j + 2*i + 1] = f.y;
        }
    }
}

// Scratch (fp16): ll (96*512*512) and p (576*256*256)
__device__ __align__(16) __half g_ll[25165824];
__device__ __align__(16) __half g_p [37748736];

// ---------------------------------------------------------------------------
// j1 fused core: (load + rowfilter, 8-wide tasks) -> smem lo/hi (38x64) ->
// branch-split col filter: warps 0-3 lo branch, warps 4-7 hi branch;
// each thread: 1 pair-col (float2) x 4 pair-rows, streaming 14 rows (LDS.64).
// Block (32,8). Out tile: 16 pair-rows x 32 pairs (64 px).
// ---------------------------------------------------------------------------
template<int W, typename T, class Writer>
static __device__ __forceinline__ void j1_core(
    const T* __restrict__ xim,
    const float* __restrict__ h0, const float* __restrict__ h1,
    int bx, int by, Writer& wr)
{
    __shared__ __align__(16) float slo[38][64];
    __shared__ __align__(16) float shi[38][64];

    const int tx = threadIdx.x, ty = threadIdx.y;
    const int tid = ty * 32 + tx;
    const int r0 = 32 * by - 3;
    const int c0 = 64 * bx - 4;

    float f0[5], f1[7];
#pragma unroll
    for (int k = 0; k < 5; k++) f0[k] = __ldg(h0 + k);
#pragma unroll
    for (int k = 0; k < 7; k++) f1[k] = __ldg(h1 + k);

    // ---- phase 1: fused load + row filter. 38 rows x 8 eight-wide tasks ----
    for (int idx = tid; idx < 38 * 8; idx += 256) {
        int rr = idx >> 3, q = idx & 7;
        int c = c0 + 8 * q;
        const T* rowp = xim + (long)refl(r0 + rr, W) * W;
        float w[16];
        if (c >= 0 && c + 15 < W) {
            load16(rowp, c, w);
        } else {
#pragma unroll
            for (int j = 0; j < 16; j++) w[j] = to_f(rowp[refl(c + j, W)]);
        }
        float o0[8], o1[8];
#pragma unroll
        for (int j = 0; j < 8; j++) {
            float s1 = 0.f;
#pragma unroll
            for (int k = 0; k < 7; k++) s1 += f1[k] * w[j + 1 + k];
            float s0 = 0.f;
#pragma unroll
            for (int k = 0; k < 5; k++) s0 += f0[k] * w[j + 2 + k];
            o0[j] = s0; o1[j] = s1;
        }
        ((float4*)slo[rr])[2*q]   = make_float4(o0[0], o0[1], o0[2], o0[3]);
        ((float4*)slo[rr])[2*q+1] = make_float4(o0[4], o0[5], o0[6], o0[7]);
        ((float4*)shi[rr])[2*q]   = make_float4(o1[0], o1[1], o1[2], o1[3]);
        ((float4*)shi[rr])[2*q+1] = make_float4(o1[4], o1[5], o1[6], o1[7]);
    }
    __syncthreads();

    // ---- phase 2: branch-split streaming col filter ----
    // A* = f0 filter (ll or hl), B* = f1 filter (lh or hh).
    const int branch = ty >> 2;        // 0: lo warps, 1: hi warps
    const int ty2 = ty & 3;
    const float (*S)[64] = branch ? shi : slo;

    float2 A0[4], A1[4], B0[4], B1[4];
#pragma unroll
    for (int u = 0; u < 4; u++) {
        A0[u] = make_float2(0,0); A1[u] = make_float2(0,0);
        B0[u] = make_float2(0,0); B1[u] = make_float2(0,0);
    }
#pragma unroll
    for (int r = 0; r < 14; r++) {
        float2 v = *(const float2*)&S[8 * ty2 + r][2 * tx];
#pragma unroll
        for (int u = 0; u < 4; u++) {
            int idx = r - 2 * u;
            if (idx < 0 || idx > 7) continue;
            if (idx <= 6)             { float c = f1[idx];   B0[u].x += c*v.x; B0[u].y += c*v.y; }
            if (idx >= 1)             { float c = f1[idx-1]; B1[u].x += c*v.x; B1[u].y += c*v.y; }
            if (idx >= 1 && idx <= 5) { float c = f0[idx-1]; A0[u].x += c*v.x; A0[u].y += c*v.y; }
            if (idx >= 2 && idx <= 6) { float c = f0[idx-2]; A1[u].x += c*v.x; A1[u].y += c*v.y; }
        }
    }

    if (branch == 0) {
#pragma unroll
        for (int u = 0; u < 4; u++) {
            float m0, m5;
            q2c_mags(B0[u].x, B0[u].y, B1[u].x, B1[u].y, m0, m5);
            wr.lo(u, A0[u], A1[u], m0, m5);
        }
    } else {
#pragma unroll
        for (int u = 0; u < 4; u++) {
            float m1, m4, m2, m3;
            q2c_mags(B0[u].x, B0[u].y, B1[u].x, B1[u].y, m1, m4);
            q2c_mags(A0[u].x, A0[u].y, A1[u].x, A1[u].y, m2, m3);
            wr.hi(u, m1, m4, m2, m3);
        }
    }
}

// ---------------------------------------------------------------------------
// Stage A writer + kernel. Grid (8,16,96), block (32,8).
// Pair-row base Yp = 16by + 4*ty2; pair col = 32bx + tx; px col = 64bx + 2tx.
// ---------------------------------------------------------------------------
struct AWriter {
    __half* llp0;   // ll at row 2*Yp, px col
    __half* pb;     // p plane (b*18+ch), row Yp, pair col
    __device__ __forceinline__ void lo(int u, float2 a, float2 bq, float m0, float m5) {
        *(__half2*)(llp0 + u * 1024)       = __floats2half2_rn(a.x, a.y);
        *(__half2*)(llp0 + u * 1024 + 512) = __floats2half2_rn(bq.x, bq.y);
        pb[u * 256]               = __float2half_rn(m0);
        pb[u * 256 + 5L * 196608] = __float2half_rn(m5);
    }
    __device__ __forceinline__ void hi(int u, float m1, float m4, float m2, float m3) {
        pb[u * 256 + 1L * 196608] = __float2half_rn(m1);
        pb[u * 256 + 4L * 196608] = __float2half_rn(m4);
        pb[u * 256 + 2L * 196608] = __float2half_rn(m2);
        pb[u * 256 + 3L * 196608] = __float2half_rn(m3);
    }
};

__global__ __launch_bounds__(256, 4) void k_fusedA(
    const float* __restrict__ x,
    const float* __restrict__ h0, const float* __restrict__ h1,
    __half* __restrict__ ll, __half* __restrict__ p)
{
    const int bx = blockIdx.x, by = blockIdx.y, img = blockIdx.z;
    const int tx = threadIdx.x, ty = threadIdx.y;
    const int ty2 = ty & 3;
    const int Yp = 16 * by + 4 * ty2;
    int b = img / 3, ch = img - 3 * b;

    AWriter wr;
    wr.llp0 = ll + (long)img * 262144 + (long)(2 * Yp) * 512 + (64 * bx + 2 * tx);
    wr.pb   = p + ((long)b * 18 + ch) * 65536 + (long)Yp * 256 + (32 * bx + tx);
    j1_core<512>(x + (long)img * 262144, h0, h1, bx, by, wr);
}

// ---------------------------------------------------------------------------
// Stage C writer + kernel. Grid (4,8,576), block (32,8).
// ---------------------------------------------------------------------------
struct CWriter {
    float* zb;   // Z (b,ch) base, row Yp, pair col
    int o1;
    __device__ __forceinline__ void lo(int u, float2 a, float2 bq, float m0, float m5) {
        float av = 0.25f * (a.x + a.y + bq.x + bq.y);
        __stcs(zb + u * 128 + (long)(1 + o1) * 49152, av);
        __stcs(zb + u * 128 + (long)(13 + o1) * 49152, m0);
        __stcs(zb + u * 128 + (long)(43 + o1) * 49152, m5);
    }
    __device__ __forceinline__ void hi(int u, float m1, float m4, float m2, float m3) {
        __stcs(zb + u * 128 + (long)(19 + o1) * 49152, m1);
        __stcs(zb + u * 128 + (long)(37 + o1) * 49152, m4);
        __stcs(zb + u * 128 + (long)(25 + o1) * 49152, m2);
        __stcs(zb + u * 128 + (long)(31 + o1) * 49152, m3);
    }
};

__global__ __launch_bounds__(256, 4) void k_fusedC(
    const __half* __restrict__ p,
    const float* __restrict__ h0, const float* __restrict__ h1,
    float* __restrict__ Z)
{
    const int bx = blockIdx.x, by = blockIdx.y, img = blockIdx.z;
    const int tx = threadIdx.x, ty = threadIdx.y;
    const int ty2 = ty & 3;
    const int Yp = 16 * by + 4 * ty2;
    int b = img / 18;
    int c18 = img - 18 * b;
    int o1 = c18 / 3;
    int ch = c18 - 3 * o1;

    CWriter wr;
    wr.zb = Z + ((long)b * 147 + ch) * 16384 + (long)Yp * 128 + (32 * bx + tx);
    wr.o1 = o1;
    j1_core<256>(p + (long)img * 65536, h0, h1, bx, by, wr);
}

// ---------------------------------------------------------------------------
// Stage B: fused (load + rowdfilt) -> smem -> coldfilt (2 out rows/thread)
// + q2c + avgpool, packed. Block (16,16): out tile 32Y x 16X. Grid (8,4,96).
// Reads fp16 ll, writes fp32 Z slots 0, 7..12 (streaming). (unchanged R15)
// ---------------------------------------------------------------------------
__global__ __launch_bounds__(256, 4) void k_fusedB(
    const __half* __restrict__ ll,
    const float* __restrict__ h0a, const float* __restrict__ h0b,
    const float* __restrict__ h1a, const float* __restrict__ h1b,
    float* __restrict__ Z)
{
    __shared__ __align__(16) float sl2[144][32];
    __shared__ __align__(16) float sh2[144][32];

    const int bx = blockIdx.x, by = blockIdx.y, img = blockIdx.z;
    const int tx = threadIdx.x, ty = threadIdx.y;
    const int tid = ty * 16 + tx;
    const __half* lim = ll + (long)img * 262144;
    const int r0 = 128 * by - 8, c0 = 64 * bx - 8;

    float fa0[10], fb0[10], fa1[10], fb1[10];
#pragma unroll
    for (int k = 0; k < 10; k++) {
        fa0[k] = __ldg(h0a + k); fb0[k] = __ldg(h0b + k);
        fa1[k] = __ldg(h1a + k); fb1[k] = __ldg(h1b + k);
    }

    for (int idx = tid; idx < 144 * 8; idx += 256) {
        int rr = idx >> 3, qq = idx & 7;
        int c = c0 + 8 * qq;
        const __half* rowp = lim + (long)refl(r0 + rr, 512) * 512;
        u64 w2[12];
        if (c >= 0 && c + 23 < 512) {
#pragma unroll
            for (int j = 0; j < 3; j++) {
                uint4 v = *(const uint4*)(rowp + c + 8 * j);
                const __half2* hv = (const __half2*)&v;
#pragma unroll
                for (int i = 0; i < 4; i++) {
                    float2 f = __half22float2(hv[i]);
                    w2[4*j + i] = pk2(f.x, f.y);
                }
            }
        } else {
            float w[24];
#pragma unroll
            for (int j = 0; j < 24; j++) w[j] = __half2float(rowp[refl(c + j, 512)]);
#pragma unroll
            for (int i = 0; i < 12; i++) w2[i] = pk2(w[2*i], w[2*i+1]);
        }
        u64 accL[2] = {0ull, 0ull}, accH[2] = {0ull, 0ull};
#pragma unroll
        for (int k = 0; k < 10; k++) {
            u64 cl = pk2(fb0[k], fa0[k]);
            u64 ch = pk2(fb1[k], fa1[k]);
#pragma unroll
            for (int j = 0; j < 2; j++) {
                fmap(accL[j], cl, w2[2*j + k]);
                fmap(accH[j], ch, w2[2*j + k]);
            }
        }
        float2 L0 = upk(accL[0]), L1 = upk(accL[1]);
        float2 H0 = upk(accH[0]), H1 = upk(accH[1]);
        ((float4*)sl2[rr])[qq] = make_float4(L0.x, L0.y, L1.x, L1.y);
        ((float4*)sh2[rr])[qq] = make_float4(H0.y, H0.x, H1.y, H1.x);
    }
    __syncthreads();

    const int Ybase = 32 * by + 2 * ty, X = 16 * bx + tx;
    int b = img / 3, ch = img - 3 * b;
    float* zb = Z + ((long)b * 147 + ch) * 16384 + ((long)Ybase * 128 + X);

    {
        u64 ll0[2] = {0,0}, ll1[2] = {0,0}, lh0[2] = {0,0}, lh1[2] = {0,0};
#pragma unroll
        for (int j = 0; j < 12; j++) {
            int lrE = 8 * ty + 2 * j, lrO = lrE + 1;
            u64 a = ((const u64*)sl2[lrE])[tx];
            u64 q = ((const u64*)sl2[lrO])[tx];
#pragma unroll
            for (int u = 0; u < 2; u++) {
                int k = j - 2 * u;
                if (k < 0 || k > 9) continue;
                fmap(ll0[u], pk2(fb0[k], fb0[k]), a);
                fmap(ll1[u], pk2(fa0[k], fa0[k]), q);
                fmap(lh0[u], pk2(fa1[k], fa1[k]), q);
                fmap(lh1[u], pk2(fb1[k], fb1[k]), a);
            }
        }
#pragma unroll
        for (int u = 0; u < 2; u++) {
            float2 L0 = upk(ll0[u]), L1 = upk(ll1[u]);
            float2 G0 = upk(lh0[u]), G1 = upk(lh1[u]);
            float s0v = 0.25f * (L0.x + L0.y + L1.x + L1.y);
            float m0, m5;
            q2c_mags(G0.x, G0.y, G1.x, G1.y, m0, m5);
            __stcs(zb + u * 128, s0v);
            __stcs(zb + u * 128 + 7L  * 49152, m0);
            __stcs(zb + u * 128 + 12L * 49152, m5);
        }
    }
    {
        u64 hl0[2] = {0,0}, hl1[2] = {0,0}, hh0[2] = {0,0}, hh1[2] = {0,0};
#pragma unroll
        for (int j = 0; j < 12; j++) {
            int lrE = 8 * ty + 2 * j, lrO = lrE + 1;
            u64 cv = ((const u64*)sh2[lrE])[tx];
            u64 dv = ((const u64*)sh2[lrO])[tx];
#pragma unroll
            for (int u = 0; u < 2; u++) {
                int k = j - 2 * u;
                if (k < 0 || k > 9) continue;
                fmap(hl0[u], pk2(fb0[k], fb0[k]), cv);
                fmap(hl1[u], pk2(fa0[k], fa0[k]), dv);
                fmap(hh0[u], pk2(fa1[k], fa1[k]), dv);
                fmap(hh1[u], pk2(fb1[k], fb1[k]), cv);
            }
        }
#pragma unroll
        for (int u = 0; u < 2; u++) {
            float2 E0 = upk(hl0[u]), E1 = upk(hl1[u]);
            float2 G0 = upk(hh0[u]), G1 = upk(hh1[u]);
            float m1, m4, m2, m3;
            q2c_mags(G0.x, G0.y, G1.x, G1.y, m1, m4);
            q2c_mags(E0.x, E0.y, E1.x, E1.y, m2, m3);
            __stcs(zb + u * 128 + 8L  * 49152, m1);
            __stcs(zb + u * 128 + 11L * 49152, m4);
            __stcs(zb + u * 128 + 9L  * 49152, m2);
            __stcs(zb + u * 128 + 10L * 49152, m3);
        }
    }
}

// ---------------------------------------------------------------------------
// Host launcher (graph-capturable)
// ---------------------------------------------------------------------------
extern "C" void kernel_launch(void* const* d_in, const int* in_sizes, int n_in,
                              void* d_out, int out_size)
{
    const float* x   = (const float*)d_in[0];
    const float* h0o = (const float*)d_in[1];
    const float* h1o = (const float*)d_in[2];
    const float* h0a = (const float*)d_in[3];
    const float* h0b = (const float*)d_in[4];
    const float* h1a = (const float*)d_in[5];
    const float* h1b = (const float*)d_in[6];
    float* Z = (float*)d_out;

    __half *ll, *p;
    cudaGetSymbolAddress((void**)&ll, g_ll);
    cudaGetSymbolAddress((void**)&p,  g_p);

    k_fusedA<<<dim3(8, 16, 96), dim3(32, 8)>>>(x, h0o, h1o, ll, p);
    k_fusedB<<<dim3(8, 4, 96),  dim3(16, 16)>>>(ll, h0a, h0b, h1a, h1b, Z);
    k_fusedC<<<dim3(4, 8, 576), dim3(32, 8)>>>(p, h0o, h1o, Z);
}